// round 9
// baseline (speedup 1.0000x reference)
#include <cuda_runtime.h>
#include <cuda_bf16.h>
#include <cstdint>

// BatchRankingLoss: G=511 groups of d=256 decoys.
// loss = sum_{g,i,j} w_ij * max(0, 1 + y_ij*(o_i - o_j)) / (G*d*(d-1))
//   y_ij = -1 if (t_i - t_j) < 0 else +1 ;  w_ij = |t_i - t_j| > 0.1
//
// Symmetry: term(i,j)==term(j,i) -> sum = 2 * sum over unordered pairs.
// Per row i: m=1..127 full weight, m=128 half weight (distance-128 pairs are
// generated by both endpoints).
//
// CTA = 256 threads = ONE group. u=tid&63 -> 4-row block (rows 4u..4u+3 in
// regs); h=tid>>6 -> 4-way column split of s (column offset from block base;
// row k sees m = s-k):
//   h=0: pairs s=4..33   (15) + prologue s=1..3
//   h=1: pairs s=34..65  (16)
//   h=2: pairs s=66..97  (16)
//   h=3: pairs s=98..127 (15) + epilogue s=128..131 (m=128 -> half weight)
// -> 511 CTAs x 8 warps = 4088 warps (~6.9/SMSP) to hide LDS/FSETP latency,
// which R8's occ=20%/issue=50% showed was the binding constraint.
//
// Packed math: smem holds NEGATED o,t (separate float arrays), so a column
// pair costs one add.rn.f32x2 for dt2 and one for dd2. Padded to 384 (first
// 128 rows duplicated) so indices never wrap.
//
// Fused reduction: group sums -> scratch; last CTA (ticket) writes d_out and
// resets the ticket -> graph-replay deterministic.

#define D      256
#define PAD    384
#define THRESH 0.1f

__device__ float    g_group_sums[4096];
__device__ unsigned g_ticket;   // zero-init; reset by last CTA each call

__device__ __forceinline__ uint64_t f32x2_add(uint64_t a, uint64_t b)
{
    uint64_t r;
    asm("add.rn.f32x2 %0, %1, %2;" : "=l"(r) : "l"(a), "l"(b));
    return r;
}
__device__ __forceinline__ uint64_t pack2(float lo, float hi)
{
    uint64_t r;
    asm("mov.b64 %0, {%1, %2};" : "=l"(r) : "f"(lo), "f"(hi));
    return r;
}
__device__ __forceinline__ void unpack2(uint64_t v, float& lo, float& hi)
{
    asm("mov.b64 {%0, %1}, %2;" : "=f"(lo), "=f"(hi) : "l"(v));
}

__device__ __forceinline__ void acc_half(float& acc, float dt, float dd)
{
    // y*do via sign-bit xor (y=-1 iff dt<0; dt==+-0 is weighted out)
    const uint32_t s =
        __float_as_uint(dd) ^ (__float_as_uint(dt) & 0x80000000u);
    const float q = fmaxf(0.0f, 1.0f + __uint_as_float(s));
    if (fabsf(dt) > THRESH) acc += q;          // predicated FADD
}

__device__ __forceinline__ void acc_neg(float& acc, float oi, float ti,
                                        float noj, float ntj)
{
    acc_half(acc, ti + ntj, oi + noj);
}

__global__ __launch_bounds__(256) void ranking_loss_kernel(
    const float* __restrict__ o_in,   // [B,1] -> [B]
    const float* __restrict__ t_in,   // [B]
    float* __restrict__ out,
    int G)
{
    __shared__ __align__(16) float no_s[PAD];   // negated o
    __shared__ __align__(16) float nt_s[PAD];   // negated t
    __shared__ float wsum[8];
    __shared__ bool  is_last;

    const int tid = threadIdx.x;
    const int u   = tid & 63;          // 4-row block index
    const int h   = tid >> 6;          // column slice
    const int g   = blockIdx.x;
    const int r   = 4 * u;

    const float4 o4 = reinterpret_cast<const float4*>(o_in)[g * 64 + u];
    const float4 t4 = reinterpret_cast<const float4*>(t_in)[g * 64 + u];

    if (h == 0) {                      // one writer per 4-row block
        no_s[r + 0] = -o4.x; no_s[r + 1] = -o4.y;
        no_s[r + 2] = -o4.z; no_s[r + 3] = -o4.w;
        nt_s[r + 0] = -t4.x; nt_s[r + 1] = -t4.y;
        nt_s[r + 2] = -t4.z; nt_s[r + 3] = -t4.w;
        if (r < 128) {                 // duplicate first 128 rows -> no wrap
            no_s[D + r + 0] = -o4.x; no_s[D + r + 1] = -o4.y;
            no_s[D + r + 2] = -o4.z; no_s[D + r + 3] = -o4.w;
            nt_s[D + r + 0] = -t4.x; nt_s[D + r + 1] = -t4.y;
            nt_s[D + r + 2] = -t4.z; nt_s[D + r + 3] = -t4.w;
        }
    }
    __syncthreads();

    const float* cno = no_s + r;       // cno[s] = -o[row r+s]
    const float* cnt = nt_s + r;

    const float oi[4] = {o4.x, o4.y, o4.z, o4.w};
    const float ti[4] = {t4.x, t4.y, t4.z, t4.w};
    uint64_t oi2[4], ti2[4];
#pragma unroll
    for (int k = 0; k < 4; ++k) {
        oi2[k] = pack2(oi[k], oi[k]);
        ti2[k] = pack2(ti[k], ti[k]);
    }

    float accA[4] = {0.f, 0.f, 0.f, 0.f};
    float accB[4] = {0.f, 0.f, 0.f, 0.f};
    float ah = 0.f;                    // m=128 half-weight accumulator

    // column slice: even start, np pairs
    const int s0 = (h == 0) ? 4 : (h == 1) ? 34 : (h == 2) ? 66 : 98;
    const int np = (h == 1 || h == 2) ? 16 : 15;
    const float* pnt = cnt + s0;
    const float* pno = cno + s0;

#pragma unroll 4
    for (int p = 0; p < np; ++p) {
        const uint64_t ntj2 =
            *reinterpret_cast<const uint64_t*>(pnt + 2 * p);  // LDS.64
        const uint64_t noj2 =
            *reinterpret_cast<const uint64_t*>(pno + 2 * p);
#pragma unroll
        for (int k = 0; k < 4; ++k) {
            float dtl, dth, ddl, ddh;
            unpack2(f32x2_add(ti2[k], ntj2), dtl, dth);
            unpack2(f32x2_add(oi2[k], noj2), ddl, ddh);
            acc_half(accA[k], dtl, ddl);
            acc_half(accB[k], dth, ddh);
        }
    }

    if (h == 0) {
        // prologue: s=1..3 (only rows with m = s-k >= 1)
        acc_neg(accA[0], oi[0], ti[0], cno[1], cnt[1]);
        acc_neg(accA[0], oi[0], ti[0], cno[2], cnt[2]);
        acc_neg(accA[1], oi[1], ti[1], cno[2], cnt[2]);
        acc_neg(accA[0], oi[0], ti[0], cno[3], cnt[3]);
        acc_neg(accA[1], oi[1], ti[1], cno[3], cnt[3]);
        acc_neg(accA[2], oi[2], ti[2], cno[3], cnt[3]);
    } else if (h == 3) {
        // epilogue: s=128..131 ; m==128 terms -> half-weight acc
        acc_neg(ah,      oi[0], ti[0], cno[128], cnt[128]);   // m=128
        acc_neg(accA[1], oi[1], ti[1], cno[128], cnt[128]);   // m=127
        acc_neg(accA[2], oi[2], ti[2], cno[128], cnt[128]);   // m=126
        acc_neg(accA[3], oi[3], ti[3], cno[128], cnt[128]);   // m=125
        acc_neg(ah,      oi[1], ti[1], cno[129], cnt[129]);   // m=128
        acc_neg(accA[2], oi[2], ti[2], cno[129], cnt[129]);
        acc_neg(accA[3], oi[3], ti[3], cno[129], cnt[129]);
        acc_neg(ah,      oi[2], ti[2], cno[130], cnt[130]);   // m=128
        acc_neg(accA[3], oi[3], ti[3], cno[130], cnt[130]);
        acc_neg(ah,      oi[3], ti[3], cno[131], cnt[131]);   // m=128
    }

    float acc = ((accA[0] + accB[0]) + (accA[1] + accB[1]))
              + ((accA[2] + accB[2]) + (accA[3] + accB[3]))
              + 0.5f * ah;

    // CTA reduce (8 warps)
#pragma unroll
    for (int off = 16; off > 0; off >>= 1)
        acc += __shfl_xor_sync(0xffffffffu, acc, off);
    if ((tid & 31) == 0) wsum[tid >> 5] = acc;
    __syncthreads();

    if (tid == 0) {
        float s = 0.f;
#pragma unroll
        for (int w = 0; w < 8; ++w) s += wsum[w];
        g_group_sums[g] = s;
        __threadfence();
        unsigned old = atomicAdd(&g_ticket, 1u);
        is_last = (old == (unsigned)(G - 1));
    }
    __syncthreads();

    if (is_last) {
        __threadfence();                    // acquire other CTAs' sums
        float v = (tid < G) ? g_group_sums[tid] : 0.f;
        if (tid + 256 < G) v += g_group_sums[tid + 256];

#pragma unroll
        for (int off = 16; off > 0; off >>= 1)
            v += __shfl_xor_sync(0xffffffffu, v, off);
        if ((tid & 31) == 0) wsum[tid >> 5] = v;
        __syncthreads();

        if (tid == 0) {
            float s = 0.f;
#pragma unroll
            for (int w = 0; w < 8; ++w) s += wsum[w];
            const float inv_n = 1.0f / ((float)G * (float)D * (float)(D - 1));
            out[0] = 2.0f * s * inv_n;      // x2: unordered -> ordered pairs
            g_ticket = 0;                   // reset for next graph replay
        }
    }
}

extern "C" void kernel_launch(void* const* d_in, const int* in_sizes, int n_in,
                              void* d_out, int out_size)
{
    const float* o = (const float*)d_in[0];  // input  [B,1] f32
    const float* t = (const float*)d_in[1];  // gdt_ts [B]   f32
    float* out = (float*)d_out;

    const int B = in_sizes[1];
    const int K = B / D;            // 512
    const int G = K - 1;            // 511 (reference skips final group)

    ranking_loss_kernel<<<G, 256>>>(o, t, out, G);
}

// round 11
// speedup vs baseline: 1.1310x; 1.1310x over previous
#include <cuda_runtime.h>
#include <cuda_bf16.h>
#include <cstdint>

// BatchRankingLoss: G=511 groups of d=256 decoys.
// loss = sum_{g,i,j} w_ij * max(0, 1 + y_ij*(o_i - o_j)) / (G*d*(d-1))
//   y_ij = -1 if (t_i - t_j) < 0 else +1 ;  w_ij = |t_i - t_j| > 0.1
//
// Symmetry: term(i,j)==term(j,i) -> sum = 2 * sum over unordered pairs.
// Per row i: m=1..127 full weight, m=128 half weight (distance-128 pairs are
// generated by both endpoints).
//
// CTA = 256 threads = ONE group. u=tid&63 -> 4-row block (rows 4u..4u+3 in
// regs); h=tid>>6 -> COMPILE-TIME 4-way column split (s = column offset from
// block base; row k sees m = s-k):
//   h=0: prologue s=1..3 + pairs s=4..33   (15 pairs)
//   h=1: pairs s=34..65  (16)
//   h=2: pairs s=66..97  (16)
//   h=3: pairs s=98..127 (15) + epilogue s=128..131 (m=128 -> half weight)
// Each slice is a fully-unrolled template body with constant offsets: every
// LDS.64 is [Rbase+imm], zero loop/address arithmetic (R9's runtime bounds
// added ~1.1M warp-instrs and erased the occupancy gain).
// h is warp-uniform -> no divergence, only I$ footprint (~12KB, fits L1.5).
//
// Packed math: smem holds NEGATED o,t (separate float arrays) so a column
// pair costs one add.rn.f32x2 for dt2 and one for dd2. Padded to 384 (first
// 128 rows duplicated) so indices never wrap.
//
// Fused reduction: group sums -> scratch; last CTA (ticket) writes d_out and
// resets the ticket -> graph-replay deterministic.

#define D      256
#define PAD    384
#define THRESH 0.1f

__device__ float    g_group_sums[4096];
__device__ unsigned g_ticket;   // zero-init; reset by last CTA each call

__device__ __forceinline__ uint64_t f32x2_add(uint64_t a, uint64_t b)
{
    uint64_t r;
    asm("add.rn.f32x2 %0, %1, %2;" : "=l"(r) : "l"(a), "l"(b));
    return r;
}
__device__ __forceinline__ uint64_t pack2(float lo, float hi)
{
    uint64_t r;
    asm("mov.b64 %0, {%1, %2};" : "=l"(r) : "f"(lo), "f"(hi));
    return r;
}
__device__ __forceinline__ void unpack2(uint64_t v, float& lo, float& hi)
{
    asm("mov.b64 {%0, %1}, %2;" : "=f"(lo), "=f"(hi) : "l"(v));
}

__device__ __forceinline__ void acc_half(float& acc, float dt, float dd)
{
    // y*do via sign-bit xor (y=-1 iff dt<0; dt==+-0 is weighted out)
    const uint32_t s =
        __float_as_uint(dd) ^ (__float_as_uint(dt) & 0x80000000u);
    const float q = fmaxf(0.0f, 1.0f + __uint_as_float(s));
    if (fabsf(dt) > THRESH) acc += q;          // predicated FADD
}

__device__ __forceinline__ void acc_neg(float& acc, float oi, float ti,
                                        float noj, float ntj)
{
    acc_half(acc, ti + ntj, oi + noj);
}

// One compile-time slice: NP packed column-pairs starting at constant S0.
template <int S0, int NP>
__device__ __forceinline__ void do_slice(const float* cno, const float* cnt,
                                         const uint64_t* oi2, const uint64_t* ti2,
                                         float* accA, float* accB)
{
#pragma unroll
    for (int p = 0; p < NP; ++p) {
        const int s = S0 + 2 * p;                          // compile-time
        const uint64_t ntj2 =
            *reinterpret_cast<const uint64_t*>(cnt + s);   // LDS.64 [R+imm]
        const uint64_t noj2 =
            *reinterpret_cast<const uint64_t*>(cno + s);
#pragma unroll
        for (int k = 0; k < 4; ++k) {
            float dtl, dth, ddl, ddh;
            unpack2(f32x2_add(ti2[k], ntj2), dtl, dth);
            unpack2(f32x2_add(oi2[k], noj2), ddl, ddh);
            acc_half(accA[k], dtl, ddl);
            acc_half(accB[k], dth, ddh);
        }
    }
}

__global__ __launch_bounds__(256) void ranking_loss_kernel(
    const float* __restrict__ o_in,   // [B,1] -> [B]
    const float* __restrict__ t_in,   // [B]
    float* __restrict__ out,
    int G)
{
    __shared__ __align__(16) float no_s[PAD];   // negated o
    __shared__ __align__(16) float nt_s[PAD];   // negated t
    __shared__ float wsum[8];
    __shared__ bool  is_last;

    const int tid = threadIdx.x;
    const int u   = tid & 63;          // 4-row block index
    const int h   = tid >> 6;          // column slice (warp-uniform)
    const int g   = blockIdx.x;
    const int r   = 4 * u;

    const float4 o4 = reinterpret_cast<const float4*>(o_in)[g * 64 + u];
    const float4 t4 = reinterpret_cast<const float4*>(t_in)[g * 64 + u];

    if (h == 0) {                      // one writer per 4-row block
        no_s[r + 0] = -o4.x; no_s[r + 1] = -o4.y;
        no_s[r + 2] = -o4.z; no_s[r + 3] = -o4.w;
        nt_s[r + 0] = -t4.x; nt_s[r + 1] = -t4.y;
        nt_s[r + 2] = -t4.z; nt_s[r + 3] = -t4.w;
        if (r < 128) {                 // duplicate first 128 rows -> no wrap
            no_s[D + r + 0] = -o4.x; no_s[D + r + 1] = -o4.y;
            no_s[D + r + 2] = -o4.z; no_s[D + r + 3] = -o4.w;
            nt_s[D + r + 0] = -t4.x; nt_s[D + r + 1] = -t4.y;
            nt_s[D + r + 2] = -t4.z; nt_s[D + r + 3] = -t4.w;
        }
    }
    __syncthreads();

    const float* cno = no_s + r;       // cno[s] = -o[row r+s]
    const float* cnt = nt_s + r;

    const float oi[4] = {o4.x, o4.y, o4.z, o4.w};
    const float ti[4] = {t4.x, t4.y, t4.z, t4.w};
    uint64_t oi2[4], ti2[4];
#pragma unroll
    for (int k = 0; k < 4; ++k) {
        oi2[k] = pack2(oi[k], oi[k]);
        ti2[k] = pack2(ti[k], ti[k]);
    }

    float accA[4] = {0.f, 0.f, 0.f, 0.f};
    float accB[4] = {0.f, 0.f, 0.f, 0.f};
    float ah = 0.f;                    // m=128 half-weight accumulator

    switch (h) {
    case 0:
        do_slice<4, 15>(cno, cnt, oi2, ti2, accA, accB);
        // prologue: s=1..3 (only rows with m = s-k >= 1)
        acc_neg(accA[0], oi[0], ti[0], cno[1], cnt[1]);
        acc_neg(accA[0], oi[0], ti[0], cno[2], cnt[2]);
        acc_neg(accA[1], oi[1], ti[1], cno[2], cnt[2]);
        acc_neg(accA[0], oi[0], ti[0], cno[3], cnt[3]);
        acc_neg(accA[1], oi[1], ti[1], cno[3], cnt[3]);
        acc_neg(accA[2], oi[2], ti[2], cno[3], cnt[3]);
        break;
    case 1:
        do_slice<34, 16>(cno, cnt, oi2, ti2, accA, accB);
        break;
    case 2:
        do_slice<66, 16>(cno, cnt, oi2, ti2, accA, accB);
        break;
    default:
        do_slice<98, 15>(cno, cnt, oi2, ti2, accA, accB);
        // epilogue: s=128..131 ; m==128 terms -> half-weight acc
        acc_neg(ah,      oi[0], ti[0], cno[128], cnt[128]);   // m=128
        acc_neg(accA[1], oi[1], ti[1], cno[128], cnt[128]);   // m=127
        acc_neg(accA[2], oi[2], ti[2], cno[128], cnt[128]);   // m=126
        acc_neg(accA[3], oi[3], ti[3], cno[128], cnt[128]);   // m=125
        acc_neg(ah,      oi[1], ti[1], cno[129], cnt[129]);   // m=128
        acc_neg(accA[2], oi[2], ti[2], cno[129], cnt[129]);
        acc_neg(accA[3], oi[3], ti[3], cno[129], cnt[129]);
        acc_neg(ah,      oi[2], ti[2], cno[130], cnt[130]);   // m=128
        acc_neg(accA[3], oi[3], ti[3], cno[130], cnt[130]);
        acc_neg(ah,      oi[3], ti[3], cno[131], cnt[131]);   // m=128
        break;
    }

    float acc = ((accA[0] + accB[0]) + (accA[1] + accB[1]))
              + ((accA[2] + accB[2]) + (accA[3] + accB[3]))
              + 0.5f * ah;

    // CTA reduce (8 warps)
#pragma unroll
    for (int off = 16; off > 0; off >>= 1)
        acc += __shfl_xor_sync(0xffffffffu, acc, off);
    if ((tid & 31) == 0) wsum[tid >> 5] = acc;
    __syncthreads();

    if (tid == 0) {
        float s = 0.f;
#pragma unroll
        for (int w = 0; w < 8; ++w) s += wsum[w];
        g_group_sums[g] = s;
        __threadfence();
        unsigned old = atomicAdd(&g_ticket, 1u);
        is_last = (old == (unsigned)(G - 1));
    }
    __syncthreads();

    if (is_last) {
        __threadfence();                    // acquire other CTAs' sums
        float v = (tid < G) ? g_group_sums[tid] : 0.f;
        if (tid + 256 < G) v += g_group_sums[tid + 256];

#pragma unroll
        for (int off = 16; off > 0; off >>= 1)
            v += __shfl_xor_sync(0xffffffffu, v, off);
        if ((tid & 31) == 0) wsum[tid >> 5] = v;
        __syncthreads();

        if (tid == 0) {
            float s = 0.f;
#pragma unroll
            for (int w = 0; w < 8; ++w) s += wsum[w];
            const float inv_n = 1.0f / ((float)G * (float)D * (float)(D - 1));
            out[0] = 2.0f * s * inv_n;      // x2: unordered -> ordered pairs
            g_ticket = 0;                   // reset for next graph replay
        }
    }
}

extern "C" void kernel_launch(void* const* d_in, const int* in_sizes, int n_in,
                              void* d_out, int out_size)
{
    const float* o = (const float*)d_in[0];  // input  [B,1] f32
    const float* t = (const float*)d_in[1];  // gdt_ts [B]   f32
    float* out = (float*)d_out;

    const int B = in_sizes[1];
    const int K = B / D;            // 512
    const int G = K - 1;            // 511 (reference skips final group)

    ranking_loss_kernel<<<G, 256>>>(o, t, out, G);
}